// round 7
// baseline (speedup 1.0000x reference)
#include <cuda_runtime.h>
#include <cuda_bf16.h>
#include <math.h>
#include <stdint.h>

#define DIMN 1024
#define SEQ 4096
#define BATCH 4
#define HEADS 16
#define DHN 64
#define KPROJ 64
#define MLPD 4096
#define EPSV 1e-5f
#define ROWS (BATCH*SEQ)

// ---------------- scratch (static device globals; allocation-free) ----------------
__device__ float g_xn[ROWS*DIMN];                 // LN1 output
__device__ float g_x2[ROWS*DIMN];                 // x + attn residual
__device__ __nv_bfloat16 g_xn2[ROWS*DIMN];        // LN2 output, bf16
__device__ __nv_bfloat16 g_hbuf[(size_t)ROWS*MLPD]; // gelu(xn2@W1+b1), bf16
__device__ __nv_bfloat16 g_w1[DIMN*MLPD];         // W1 bf16 [K=1024][N=4096]
__device__ __nv_bfloat16 g_w2[MLPD*DIMN];         // W2 bf16 [K=4096][N=1024]
__device__ float g_m[BATCH*DIMN];                 // sum_s xn
__device__ float g_A[BATCH*DIMN];                 // m @ Wk
__device__ float g_Ap[BATCH*DIMN];                // m @ Wv
__device__ float g_u[BATCH*DIMN*HEADS];           // [b][j][h]
__device__ float g_G[BATCH*HEADS*DIMN];           // [b][h][j]
__device__ float g_Bsum[KPROJ];
__device__ float g_Bpsum[KPROJ];

// ---------------- helpers ----------------
__device__ __forceinline__ uint32_t smem_u32(const void* p){
    return (uint32_t)__cvta_generic_to_shared(p);
}
__device__ __forceinline__ void cp16(uint32_t s, const void* g){
    asm volatile("cp.async.cg.shared.global [%0], [%1], 16;\n" :: "r"(s), "l"(g));
}
__device__ __forceinline__ void cp_commit(){ asm volatile("cp.async.commit_group;\n" ::: "memory"); }
__device__ __forceinline__ void ldsm_x4(uint32_t &r0,uint32_t &r1,uint32_t &r2,uint32_t &r3, uint32_t a){
    asm volatile("ldmatrix.sync.aligned.m8n8.x4.shared.b16 {%0,%1,%2,%3}, [%4];\n"
        : "=r"(r0),"=r"(r1),"=r"(r2),"=r"(r3) : "r"(a));
}
__device__ __forceinline__ void ldsm_x4_t(uint32_t &r0,uint32_t &r1,uint32_t &r2,uint32_t &r3, uint32_t a){
    asm volatile("ldmatrix.sync.aligned.m8n8.x4.trans.shared.b16 {%0,%1,%2,%3}, [%4];\n"
        : "=r"(r0),"=r"(r1),"=r"(r2),"=r"(r3) : "r"(a));
}
__device__ __forceinline__ void mma_bf16(float c[4], uint32_t a0,uint32_t a1,uint32_t a2,uint32_t a3,
                                         uint32_t b0,uint32_t b1){
    asm volatile("mma.sync.aligned.m16n8k16.row.col.f32.bf16.bf16.f32 "
        "{%0,%1,%2,%3},{%4,%5,%6,%7},{%8,%9},{%0,%1,%2,%3};\n"
        : "+f"(c[0]),"+f"(c[1]),"+f"(c[2]),"+f"(c[3])
        : "r"(a0),"r"(a1),"r"(a2),"r"(a3),"r"(b0),"r"(b1));
}
__device__ __forceinline__ float gelu_exact(float v){
    return 0.5f*v*(1.0f+erff(v*0.70710678118654752f));
}

// ---------------- small kernels (unchanged, proven) ----------------
__global__ void zero_small_kernel(){
    int i = blockIdx.x*256 + threadIdx.x;
    if (i < BATCH*DIMN) g_m[i] = 0.f;
    if (i < KPROJ){ g_Bsum[i]=0.f; g_Bpsum[i]=0.f; }
}

__global__ __launch_bounds__(256) void ln1_kernel(const float* __restrict__ x,
        const float* __restrict__ g, const float* __restrict__ b){
    int row = blockIdx.x; int tid = threadIdx.x;
    __shared__ float sred[512];
    float4 v = ((const float4*)(x + (size_t)row*DIMN))[tid];
    float s  = v.x+v.y+v.z+v.w;
    float sq = v.x*v.x+v.y*v.y+v.z*v.z+v.w*v.w;
    sred[tid]=s; sred[256+tid]=sq; __syncthreads();
    #pragma unroll
    for (int off=128; off; off>>=1){
        if (tid<off){ sred[tid]+=sred[tid+off]; sred[256+tid]+=sred[256+tid+off]; }
        __syncthreads();
    }
    float mu  = sred[0]*(1.0f/DIMN);
    float var = sred[256]*(1.0f/DIMN) - mu*mu;
    float rs  = rsqrtf(var + EPSV);
    float4 gv = ((const float4*)g)[tid];
    float4 bv = ((const float4*)b)[tid];
    float4 o;
    o.x=(v.x-mu)*rs*gv.x+bv.x; o.y=(v.y-mu)*rs*gv.y+bv.y;
    o.z=(v.z-mu)*rs*gv.z+bv.z; o.w=(v.w-mu)*rs*gv.w+bv.w;
    ((float4*)(g_xn + (size_t)row*DIMN))[tid] = o;
}

__global__ void colsum_xn_kernel(){
    int b = blockIdx.x, chunk = blockIdx.y, j = threadIdx.x;
    const float* base = g_xn + ((size_t)(b*SEQ + chunk*128))*DIMN + j;
    float acc = 0.f;
    #pragma unroll 4
    for (int s=0; s<128; s++) acc += base[(size_t)s*DIMN];
    atomicAdd(&g_m[b*DIMN + j], acc);
}

__global__ void colsum_ef_kernel(const float* __restrict__ E, const float* __restrict__ Fm){
    const float* src = blockIdx.x ? Fm : E;
    float* dst = blockIdx.x ? g_Bpsum : g_Bsum;
    int kk = threadIdx.x;
    int s0 = blockIdx.y*256;
    float acc = 0.f;
    for (int s=0; s<256; s++) acc += src[(size_t)(s0+s)*KPROJ + kk];
    atomicAdd(&dst[kk], acc);
}

__global__ __launch_bounds__(256) void gemv_AAp_kernel(const float* __restrict__ Wk,
        const float* __restrict__ Wv){
    int b = blockIdx.y;
    int col = blockIdx.x*256 + threadIdx.x;
    __shared__ float sm[DIMN];
    for (int j=threadIdx.x; j<DIMN; j+=256) sm[j] = g_m[b*DIMN + j];
    __syncthreads();
    float ak=0.f, av=0.f;
    for (int j=0; j<DIMN; j++){
        float mj = sm[j];
        ak += mj * Wk[(size_t)j*DIMN + col];
        av += mj * Wv[(size_t)j*DIMN + col];
    }
    g_A [b*DIMN + col] = ak;
    g_Ap[b*DIMN + col] = av;
}

__global__ __launch_bounds__(256) void compute_u_kernel(const float* __restrict__ Wq){
    int b = blockIdx.x;
    __shared__ float sA[DIMN];
    for (int i=threadIdx.x; i<DIMN; i+=256) sA[i] = g_A[b*DIMN + i];
    __syncthreads();
    int j = blockIdx.y*16 + (threadIdx.x >> 4);
    int h = threadIdx.x & 15;
    const float* wrow = Wq + (size_t)j*DIMN + h*DHN;
    const float* av = sA + h*DHN;
    float acc = 0.f;
    #pragma unroll
    for (int d=0; d<DHN; d++) acc += wrow[d]*av[d];
    g_u[((size_t)b*DIMN + j)*HEADS + h] = acc;
}

__global__ __launch_bounds__(256) void compute_G_kernel(const float* __restrict__ Wo){
    int b = blockIdx.x, h = blockIdx.y;
    __shared__ float sa[DHN];
    if (threadIdx.x < DHN) sa[threadIdx.x] = g_Ap[b*DIMN + h*DHN + threadIdx.x];
    __syncthreads();
    float4 acc = {0.f,0.f,0.f,0.f};
    #pragma unroll 8
    for (int d=0; d<DHN; d++){
        float a = sa[d];
        float4 w = ((const float4*)(Wo + (size_t)(h*DHN + d)*DIMN))[threadIdx.x];
        acc.x += a*w.x; acc.y += a*w.y; acc.z += a*w.z; acc.w += a*w.w;
    }
    ((float4*)(g_G + (size_t)(b*HEADS + h)*DIMN))[threadIdx.x] = acc;
}

__global__ __launch_bounds__(256) void attn_apply_kernel(const float* __restrict__ x,
        const float* __restrict__ bo, const float* __restrict__ g2, const float* __restrict__ b2){
    int row = blockIdx.x;
    int b = row / SEQ;
    int tid = threadIdx.x;
    __shared__ float sxn[DIMN];
    __shared__ float sred[512];
    __shared__ float sw[HEADS];
    __shared__ float sB[KPROJ], sBp[KPROJ];

    ((float4*)sxn)[tid] = ((const float4*)(g_xn + (size_t)row*DIMN))[tid];
    if (tid < KPROJ){ sB[tid]=g_Bsum[tid]; sBp[tid]=g_Bpsum[tid]; }
    __syncthreads();

    int h = tid & 15, grp = tid >> 4;
    const float* ub = g_u + (size_t)b*DIMN*HEADS;
    float acc = 0.f;
    for (int jj = grp; jj < DIMN; jj += 16) acc += sxn[jj] * ub[(size_t)jj*HEADS + h];
    sred[tid] = acc;
    __syncthreads();
    #pragma unroll
    for (int off=128; off>=16; off>>=1){
        if (tid < off) sred[tid] += sred[tid+off];
        __syncthreads();
    }
    if (tid < HEADS){
        float c = sred[tid] * 0.125f;
        float mx = -INFINITY;
        #pragma unroll 8
        for (int k2=0; k2<KPROJ; k2++) mx = fmaxf(mx, c*sB[k2]);
        float se=0.f, sv=0.f;
        for (int k2=0; k2<KPROJ; k2++){
            float e = expf(c*sB[k2]-mx);
            se += e; sv += e*sBp[k2];
        }
        sw[tid] = sv/se;
    }
    __syncthreads();

    float4 xv = ((const float4*)(x + (size_t)row*DIMN))[tid];
    float4 bov = ((const float4*)bo)[tid];
    float4 o = {xv.x+bov.x, xv.y+bov.y, xv.z+bov.z, xv.w+bov.w};
    const float* Gb = g_G + (size_t)b*HEADS*DIMN;
    #pragma unroll
    for (int hh=0; hh<HEADS; hh++){
        float w = sw[hh];
        float4 g4 = ((const float4*)(Gb + (size_t)hh*DIMN))[tid];
        o.x += w*g4.x; o.y += w*g4.y; o.z += w*g4.z; o.w += w*g4.w;
    }
    ((float4*)(g_x2 + (size_t)row*DIMN))[tid] = o;

    float s  = o.x+o.y+o.z+o.w;
    float sq = o.x*o.x+o.y*o.y+o.z*o.z+o.w*o.w;
    sred[tid]=s; sred[256+tid]=sq; __syncthreads();
    #pragma unroll
    for (int off=128; off; off>>=1){
        if (tid<off){ sred[tid]+=sred[tid+off]; sred[256+tid]+=sred[256+tid+off]; }
        __syncthreads();
    }
    float mu  = sred[0]*(1.0f/DIMN);
    float var = sred[256]*(1.0f/DIMN) - mu*mu;
    float rs  = rsqrtf(var + EPSV);
    float4 gv = ((const float4*)g2)[tid];
    float4 b2v = ((const float4*)b2)[tid];
    float v0=(o.x-mu)*rs*gv.x+b2v.x, v1=(o.y-mu)*rs*gv.y+b2v.y;
    float v2=(o.z-mu)*rs*gv.z+b2v.z, v3=(o.w-mu)*rs*gv.w+b2v.w;
    __nv_bfloat162* dst = (__nv_bfloat162*)(g_xn2 + (size_t)row*DIMN);
    dst[tid*2]   = __floats2bfloat162_rn(v0, v1);
    dst[tid*2+1] = __floats2bfloat162_rn(v2, v3);
}

__global__ void cvt_bf16_kernel(const float* __restrict__ src, __nv_bfloat16* __restrict__ dst, int n4){
    int i = blockIdx.x*256 + threadIdx.x;
    if (i < n4){
        float4 v = ((const float4*)src)[i];
        ((__nv_bfloat162*)dst)[i*2]   = __floats2bfloat162_rn(v.x, v.y);
        ((__nv_bfloat162*)dst)[i*2+1] = __floats2bfloat162_rn(v.z, v.w);
    }
}

// ---------------- bf16 mma GEMM, 256x128x32 CTA tile, warp tile 64x64, 4-stage ring ----------------
// MODE 0: g_hbuf = gelu(g_xn2 @ g_w1 + b1)          (M=16384,N=4096,K=1024) -> bf16
// MODE 1: out    = g_x2 + g_hbuf @ g_w2 + b2        (M=16384,N=1024,K=4096) -> fp32
#define GST 4
#define GBM 256
#define GBN 128
#define AST 40                        // 32 + 8 pad (bf16 elems)
#define BST 136                       // 128 + 8 pad
#define STAGE_ELE (GBM*AST + 32*BST)  // 10240 + 4352 = 14592 bf16 = 29184 B
#define GEMM_SMEM (GST*STAGE_ELE*2)   // 116736 B

template<int MODE>
__global__ __launch_bounds__(256,1) void gemm_bf16_kernel(const float* __restrict__ bias,
                                                          float* __restrict__ Cf){
    constexpr int N = (MODE==0) ? MLPD : DIMN;
    constexpr int K = (MODE==0) ? DIMN : MLPD;
    constexpr int nk = K / 32;
    const __nv_bfloat16* A = (MODE==0) ? g_xn2 : g_hbuf;
    const __nv_bfloat16* B = (MODE==0) ? g_w1  : g_w2;   // [K][N]

    extern __shared__ __nv_bfloat16 smem[];

    int bm = blockIdx.y * GBM;
    int bn = blockIdx.x * GBN;
    int tid = threadIdx.x;
    int warp = tid >> 5, lane = tid & 31;
    int wm = (warp & 3) * 64;     // 4 M-bands
    int wn = (warp >> 2) * 64;    // 2 N-bands

    float acc[4][8][4];
    #pragma unroll
    for (int i=0;i<4;i++)
        #pragma unroll
        for (int j=0;j<8;j++)
            #pragma unroll
            for (int k=0;k<4;k++) acc[i][j][k]=0.f;

    auto load_stage = [&](int st, int kc){
        int k0 = kc * 32;
        __nv_bfloat16* As = smem + st*STAGE_ELE;
        __nv_bfloat16* Bs = As + GBM*AST;
        #pragma unroll
        for (int i=0; i<4; i++){                 // A: 256 rows x 4 chunks of 8
            int ch = tid + i*256;
            int r = ch >> 2, c = (ch & 3) << 3;
            cp16(smem_u32(As + r*AST + c), A + (size_t)(bm + r)*K + k0 + c);
        }
        #pragma unroll
        for (int i=0; i<2; i++){                 // B: 32 rows x 16 chunks of 8
            int ch = tid + i*256;
            int r = ch >> 4, c = (ch & 15) << 3;
            cp16(smem_u32(Bs + r*BST + c), B + (size_t)(k0 + r)*N + bn + c);
        }
        cp_commit();
    };

    // prologue: stages 0..2
    #pragma unroll
    for (int p=0; p<GST-1; p++) load_stage(p, p);

    for (int kt = 0; kt < nk; kt++){
        int cur = kt & (GST-1);
        asm volatile("cp.async.wait_group %0;\n" :: "n"(GST-2) : "memory");
        __syncthreads();

        if (kt + GST - 1 < nk) load_stage((kt + GST - 1) & (GST-1), kt + GST - 1);
        else cp_commit();

        const __nv_bfloat16* As = smem + cur*STAGE_ELE;
        const __nv_bfloat16* Bs = As + GBM*AST;

        #pragma unroll
        for (int ks=0; ks<2; ks++){
            int k16 = ks*16;
            uint32_t af[4][4], bfr[8][2];
            #pragma unroll
            for (int mi=0; mi<4; mi++){
                int r = wm + mi*16 + (lane & 15);
                int c = k16 + ((lane >> 4) << 3);
                ldsm_x4(af[mi][0],af[mi][1],af[mi][2],af[mi][3],
                        smem_u32(As + r*AST + c));
            }
            #pragma unroll
            for (int nj=0; nj<4; nj++){
                int r = k16 + (((lane>>3)&1) << 3) + (lane & 7);
                int c = wn + nj*16 + ((lane >> 4) << 3);
                uint32_t t0,t1,t2,t3;
                ldsm_x4_t(t0,t1,t2,t3, smem_u32(Bs + r*BST + c));
                bfr[nj*2][0]=t0; bfr[nj*2][1]=t1;
                bfr[nj*2+1][0]=t2; bfr[nj*2+1][1]=t3;
            }
            #pragma unroll
            for (int mi=0; mi<4; mi++)
                #pragma unroll
                for (int ni=0; ni<8; ni++)
                    mma_bf16(acc[mi][ni], af[mi][0],af[mi][1],af[mi][2],af[mi][3],
                             bfr[ni][0], bfr[ni][1]);
        }
    }

    // epilogue
    #pragma unroll
    for (int mi=0; mi<4; mi++){
        #pragma unroll
        for (int ni=0; ni<8; ni++){
            int r = bm + wm + mi*16 + (lane >> 2);
            int c = bn + wn + ni*8 + (lane & 3)*2;
            float* a = acc[mi][ni];
            float bx = bias[c], by = bias[c+1];
            if (MODE == 0){
                float v0 = gelu_exact(a[0]+bx), v1 = gelu_exact(a[1]+by);
                float v2 = gelu_exact(a[2]+bx), v3 = gelu_exact(a[3]+by);
                *(__nv_bfloat162*)(g_hbuf + (size_t)r*N + c)     = __floats2bfloat162_rn(v0,v1);
                *(__nv_bfloat162*)(g_hbuf + (size_t)(r+8)*N + c) = __floats2bfloat162_rn(v2,v3);
            } else {
                size_t o0 = (size_t)r*N + c, o1 = (size_t)(r+8)*N + c;
                float2 r0 = *(const float2*)(g_x2 + o0);
                float2 r1 = *(const float2*)(g_x2 + o1);
                *(float2*)(Cf + o0) = make_float2(a[0]+bx+r0.x, a[1]+by+r0.y);
                *(float2*)(Cf + o1) = make_float2(a[2]+bx+r1.x, a[3]+by+r1.y);
            }
        }
    }
}

// ---------------- launch ----------------
extern "C" void kernel_launch(void* const* d_in, const int* in_sizes, int n_in,
                              void* d_out, int out_size){
    const float* x     = (const float*)d_in[0];
    const float* Wq    = (const float*)d_in[1];
    const float* Wk    = (const float*)d_in[2];
    const float* Wv    = (const float*)d_in[3];
    const float* E     = (const float*)d_in[4];
    const float* Fm    = (const float*)d_in[5];
    const float* Wo    = (const float*)d_in[6];
    const float* bo    = (const float*)d_in[7];
    const float* ln1_g = (const float*)d_in[8];
    const float* ln1_b = (const float*)d_in[9];
    const float* ln2_g = (const float*)d_in[10];
    const float* ln2_b = (const float*)d_in[11];
    const float* W1    = (const float*)d_in[12];
    const float* b1    = (const float*)d_in[13];
    const float* W2    = (const float*)d_in[14];
    const float* b2    = (const float*)d_in[15];
    float* out = (float*)d_out;

    cudaFuncSetAttribute(gemm_bf16_kernel<0>, cudaFuncAttributeMaxDynamicSharedMemorySize, GEMM_SMEM);
    cudaFuncSetAttribute(gemm_bf16_kernel<1>, cudaFuncAttributeMaxDynamicSharedMemorySize, GEMM_SMEM);

    zero_small_kernel<<<16, 256>>>();
    ln1_kernel<<<ROWS, 256>>>(x, ln1_g, ln1_b);
    colsum_xn_kernel<<<dim3(BATCH, 32), 1024>>>();
    colsum_ef_kernel<<<dim3(2, 16), 64>>>(E, Fm);
    gemv_AAp_kernel<<<dim3(4, BATCH), 256>>>(Wk, Wv);
    compute_u_kernel<<<dim3(BATCH, 64), 256>>>(Wq);
    compute_G_kernel<<<dim3(BATCH, HEADS), 256>>>(Wo);
    attn_apply_kernel<<<ROWS, 256>>>(x, bo, ln2_g, ln2_b);

    cvt_bf16_kernel<<<(DIMN*MLPD/4 + 255)/256, 256>>>(W1, g_w1, DIMN*MLPD/4);
    cvt_bf16_kernel<<<(MLPD*DIMN/4 + 255)/256, 256>>>(W2, g_w2, MLPD*DIMN/4);

    gemm_bf16_kernel<0><<<dim3(MLPD/GBN, ROWS/GBM), 256, GEMM_SMEM>>>(b1, nullptr);
    gemm_bf16_kernel<1><<<dim3(DIMN/GBN, ROWS/GBM), 256, GEMM_SMEM>>>(b2, out);
}

// round 10
// speedup vs baseline: 1.1974x; 1.1974x over previous
#include <cuda_runtime.h>
#include <cuda_bf16.h>
#include <math.h>
#include <stdint.h>

#define DIMN 1024
#define SEQ 4096
#define BATCH 4
#define HEADS 16
#define DHN 64
#define KPROJ 64
#define MLPD 4096
#define EPSV 1e-5f
#define ROWS (BATCH*SEQ)

// ---------------- scratch (static device globals; allocation-free) ----------------
__device__ float g_xn[ROWS*DIMN];                   // LN1 output
__device__ float g_x2[ROWS*DIMN];                   // x + attn residual
// K-chunked, pre-swizzled activations: [kc][ROWS][64] bf16
__device__ __nv_bfloat16 g_xn2[ROWS*DIMN];
__device__ __nv_bfloat16 g_hbuf[(size_t)ROWS*MLPD];
// pre-packed, pre-swizzled weights: [nb][kc][64][128] bf16
__device__ __nv_bfloat16 g_w1p[DIMN*MLPD];
__device__ __nv_bfloat16 g_w2p[MLPD*DIMN];
__device__ float g_m[BATCH*DIMN];
__device__ float g_A[BATCH*DIMN];
__device__ float g_Ap[BATCH*DIMN];
__device__ float g_u[BATCH*DIMN*HEADS];
__device__ float g_G[BATCH*HEADS*DIMN];
__device__ float g_Bsum[KPROJ];
__device__ float g_Bpsum[KPROJ];

// ---------------- helpers ----------------
__device__ __forceinline__ uint32_t smem_u32(const void* p){
    return (uint32_t)__cvta_generic_to_shared(p);
}
__device__ __forceinline__ void ldsm_x4(uint32_t &r0,uint32_t &r1,uint32_t &r2,uint32_t &r3, uint32_t a){
    asm volatile("ldmatrix.sync.aligned.m8n8.x4.shared.b16 {%0,%1,%2,%3}, [%4];\n"
        : "=r"(r0),"=r"(r1),"=r"(r2),"=r"(r3) : "r"(a));
}
__device__ __forceinline__ void ldsm_x4_t(uint32_t &r0,uint32_t &r1,uint32_t &r2,uint32_t &r3, uint32_t a){
    asm volatile("ldmatrix.sync.aligned.m8n8.x4.trans.shared.b16 {%0,%1,%2,%3}, [%4];\n"
        : "=r"(r0),"=r"(r1),"=r"(r2),"=r"(r3) : "r"(a));
}
__device__ __forceinline__ void mma_bf16(float c[4], uint32_t a0,uint32_t a1,uint32_t a2,uint32_t a3,
                                         uint32_t b0,uint32_t b1){
    asm volatile("mma.sync.aligned.m16n8k16.row.col.f32.bf16.bf16.f32 "
        "{%0,%1,%2,%3},{%4,%5,%6,%7},{%8,%9},{%0,%1,%2,%3};\n"
        : "+f"(c[0]),"+f"(c[1]),"+f"(c[2]),"+f"(c[3])
        : "r"(a0),"r"(a1),"r"(a2),"r"(a3),"r"(b0),"r"(b1));
}
__device__ __forceinline__ float gelu_exact(float v){
    return 0.5f*v*(1.0f+erff(v*0.70710678118654752f));
}
__device__ __forceinline__ void mbar_init(uint32_t mbar, uint32_t cnt){
    asm volatile("mbarrier.init.shared.b64 [%0], %1;" :: "r"(mbar), "r"(cnt) : "memory");
}
__device__ __forceinline__ void mbar_expect_tx(uint32_t mbar, uint32_t bytes){
    asm volatile("mbarrier.arrive.expect_tx.shared.b64 _, [%0], %1;"
        :: "r"(mbar), "r"(bytes) : "memory");
}
__device__ __forceinline__ void bulk_g2s(uint32_t dst, const void* src, uint32_t bytes, uint32_t mbar){
    asm volatile("cp.async.bulk.shared::cluster.global.mbarrier::complete_tx::bytes [%0], [%1], %2, [%3];"
        :: "r"(dst), "l"(src), "r"(bytes), "r"(mbar) : "memory");
}
__device__ __forceinline__ void mbar_wait(uint32_t mbar, uint32_t parity){
    asm volatile("{\n\t.reg .pred P;\n"
        "WLP%=:\n\tmbarrier.try_wait.parity.acquire.cta.shared::cta.b64 P, [%0], %1, 0x989680;\n"
        "\t@P bra WDN%=;\n\tbra WLP%=;\nWDN%=:\n\t}"
        :: "r"(mbar), "r"(parity) : "memory");
}
#define FENCE_ASYNC() asm volatile("fence.proxy.async.shared::cta;" ::: "memory")

// ---------------- small kernels ----------------
__global__ void zero_small_kernel(){
    int i = blockIdx.x*256 + threadIdx.x;
    if (i < BATCH*DIMN) g_m[i] = 0.f;
    if (i < KPROJ){ g_Bsum[i]=0.f; g_Bpsum[i]=0.f; }
}

__global__ __launch_bounds__(256) void ln1_kernel(const float* __restrict__ x,
        const float* __restrict__ g, const float* __restrict__ b){
    int row = blockIdx.x; int tid = threadIdx.x;
    __shared__ float sred[512];
    float4 v = ((const float4*)(x + (size_t)row*DIMN))[tid];
    float s  = v.x+v.y+v.z+v.w;
    float sq = v.x*v.x+v.y*v.y+v.z*v.z+v.w*v.w;
    sred[tid]=s; sred[256+tid]=sq; __syncthreads();
    #pragma unroll
    for (int off=128; off; off>>=1){
        if (tid<off){ sred[tid]+=sred[tid+off]; sred[256+tid]+=sred[256+tid+off]; }
        __syncthreads();
    }
    float mu  = sred[0]*(1.0f/DIMN);
    float var = sred[256]*(1.0f/DIMN) - mu*mu;
    float rs  = rsqrtf(var + EPSV);
    float4 gv = ((const float4*)g)[tid];
    float4 bv = ((const float4*)b)[tid];
    float4 o;
    o.x=(v.x-mu)*rs*gv.x+bv.x; o.y=(v.y-mu)*rs*gv.y+bv.y;
    o.z=(v.z-mu)*rs*gv.z+bv.z; o.w=(v.w-mu)*rs*gv.w+bv.w;
    ((float4*)(g_xn + (size_t)row*DIMN))[tid] = o;
}

__global__ void colsum_xn_kernel(){
    int b = blockIdx.x, chunk = blockIdx.y, j = threadIdx.x;
    const float* base = g_xn + ((size_t)(b*SEQ + chunk*128))*DIMN + j;
    float acc = 0.f;
    #pragma unroll 4
    for (int s=0; s<128; s++) acc += base[(size_t)s*DIMN];
    atomicAdd(&g_m[b*DIMN + j], acc);
}

__global__ void colsum_ef_kernel(const float* __restrict__ E, const float* __restrict__ Fm){
    const float* src = blockIdx.x ? Fm : E;
    float* dst = blockIdx.x ? g_Bpsum : g_Bsum;
    int kk = threadIdx.x;
    int s0 = blockIdx.y*256;
    float acc = 0.f;
    for (int s=0; s<256; s++) acc += src[(size_t)(s0+s)*KPROJ + kk];
    atomicAdd(&dst[kk], acc);
}

__global__ __launch_bounds__(256) void gemv_AAp_kernel(const float* __restrict__ Wk,
        const float* __restrict__ Wv){
    int b = blockIdx.y;
    int col = blockIdx.x*256 + threadIdx.x;
    __shared__ float sm[DIMN];
    for (int j=threadIdx.x; j<DIMN; j+=256) sm[j] = g_m[b*DIMN + j];
    __syncthreads();
    float ak=0.f, av=0.f;
    for (int j=0; j<DIMN; j++){
        float mj = sm[j];
        ak += mj * Wk[(size_t)j*DIMN + col];
        av += mj * Wv[(size_t)j*DIMN + col];
    }
    g_A [b*DIMN + col] = ak;
    g_Ap[b*DIMN + col] = av;
}

__global__ __launch_bounds__(256) void compute_u_kernel(const float* __restrict__ Wq){
    int b = blockIdx.x;
    __shared__ float sA[DIMN];
    for (int i=threadIdx.x; i<DIMN; i+=256) sA[i] = g_A[b*DIMN + i];
    __syncthreads();
    int j = blockIdx.y*16 + (threadIdx.x >> 4);
    int h = threadIdx.x & 15;
    const float* wrow = Wq + (size_t)j*DIMN + h*DHN;
    const float* av = sA + h*DHN;
    float acc = 0.f;
    #pragma unroll
    for (int d=0; d<DHN; d++) acc += wrow[d]*av[d];
    g_u[((size_t)b*DIMN + j)*HEADS + h] = acc;
}

__global__ __launch_bounds__(256) void compute_G_kernel(const float* __restrict__ Wo){
    int b = blockIdx.x, h = blockIdx.y;
    __shared__ float sa[DHN];
    if (threadIdx.x < DHN) sa[threadIdx.x] = g_Ap[b*DIMN + h*DHN + threadIdx.x];
    __syncthreads();
    float4 acc = {0.f,0.f,0.f,0.f};
    #pragma unroll 8
    for (int d=0; d<DHN; d++){
        float a = sa[d];
        float4 w = ((const float4*)(Wo + (size_t)(h*DHN + d)*DIMN))[threadIdx.x];
        acc.x += a*w.x; acc.y += a*w.y; acc.z += a*w.z; acc.w += a*w.w;
    }
    ((float4*)(g_G + (size_t)(b*HEADS + h)*DIMN))[threadIdx.x] = acc;
}

// fused attn + residual + LN2; writes xn2 in K-chunked swizzled layout
__global__ __launch_bounds__(256) void attn_apply_kernel(const float* __restrict__ x,
        const float* __restrict__ bo, const float* __restrict__ g2, const float* __restrict__ b2){
    int row = blockIdx.x;
    int b = row / SEQ;
    int tid = threadIdx.x;
    __shared__ float sxn[DIMN];
    __shared__ float sred[512];
    __shared__ float sw[HEADS];
    __shared__ float sB[KPROJ], sBp[KPROJ];

    ((float4*)sxn)[tid] = ((const float4*)(g_xn + (size_t)row*DIMN))[tid];
    if (tid < KPROJ){ sB[tid]=g_Bsum[tid]; sBp[tid]=g_Bpsum[tid]; }
    __syncthreads();

    int h = tid & 15, grp = tid >> 4;
    const float* ub = g_u + (size_t)b*DIMN*HEADS;
    float acc = 0.f;
    for (int jj = grp; jj < DIMN; jj += 16) acc += sxn[jj] * ub[(size_t)jj*HEADS + h];
    sred[tid] = acc;
    __syncthreads();
    #pragma unroll
    for (int off=128; off>=16; off>>=1){
        if (tid < off) sred[tid] += sred[tid+off];
        __syncthreads();
    }
    if (tid < HEADS){
        float c = sred[tid] * 0.125f;
        float mx = -INFINITY;
        #pragma unroll 8
        for (int k2=0; k2<KPROJ; k2++) mx = fmaxf(mx, c*sB[k2]);
        float se=0.f, sv=0.f;
        for (int k2=0; k2<KPROJ; k2++){
            float e = expf(c*sB[k2]-mx);
            se += e; sv += e*sBp[k2];
        }
        sw[tid] = sv/se;
    }
    __syncthreads();

    float4 xv = ((const float4*)(x + (size_t)row*DIMN))[tid];
    float4 bov = ((const float4*)bo)[tid];
    float4 o = {xv.x+bov.x, xv.y+bov.y, xv.z+bov.z, xv.w+bov.w};
    const float* Gb = g_G + (size_t)b*HEADS*DIMN;
    #pragma unroll
    for (int hh=0; hh<HEADS; hh++){
        float w = sw[hh];
        float4 g4 = ((const float4*)(Gb + (size_t)hh*DIMN))[tid];
        o.x += w*g4.x; o.y += w*g4.y; o.z += w*g4.z; o.w += w*g4.w;
    }
    ((float4*)(g_x2 + (size_t)row*DIMN))[tid] = o;

    float s  = o.x+o.y+o.z+o.w;
    float sq = o.x*o.x+o.y*o.y+o.z*o.z+o.w*o.w;
    sred[tid]=s; sred[256+tid]=sq; __syncthreads();
    #pragma unroll
    for (int off=128; off; off>>=1){
        if (tid<off){ sred[tid]+=sred[tid+off]; sred[256+tid]+=sred[256+tid+off]; }
        __syncthreads();
    }
    float mu  = sred[0]*(1.0f/DIMN);
    float var = sred[256]*(1.0f/DIMN) - mu*mu;
    float rs  = rsqrtf(var + EPSV);
    float4 gv = ((const float4*)g2)[tid];
    float4 b2v = ((const float4*)b2)[tid];
    float v0=(o.x-mu)*rs*gv.x+b2v.x, v1=(o.y-mu)*rs*gv.y+b2v.y;
    float v2=(o.z-mu)*rs*gv.z+b2v.z, v3=(o.w-mu)*rs*gv.w+b2v.w;

    // chunked + swizzled write: c0 = tid*4 covers elems [c0, c0+3]
    int c0 = tid*4;
    int kc = c0 >> 6, cc = c0 & 63, g = cc >> 3;
    int gp = g ^ (row & 7);
    uint2 val;
    __nv_bfloat162 p0 = __floats2bfloat162_rn(v0, v1);
    __nv_bfloat162 p1 = __floats2bfloat162_rn(v2, v3);
    val.x = *(uint32_t*)&p0; val.y = *(uint32_t*)&p1;
    *(uint2*)((char*)g_xn2 + ((size_t)kc*ROWS + row)*128 + gp*16 + (cc & 7)*2) = val;
}

// pack W [K][N] fp32 -> [nb][kc][kr 0..63][128 cols swizzled] bf16
__global__ __launch_bounds__(256) void pack_w_kernel(const float* __restrict__ src,
        __nv_bfloat16* __restrict__ dst, int Kdim, int Ndim){
    int t = blockIdx.x*256 + threadIdx.x;          // one 8-elem granule
    int KCn = Kdim >> 6;
    int g  = t & 15;
    int kr = (t >> 4) & 63;
    int rest = t >> 10;         // nb*KCn + kc
    int kc = rest % KCn;
    int nb = rest / KCn;
    if (nb >= (Ndim >> 7)) return;
    int k = kc*64 + kr;
    int n = nb*128 + g*8;
    const float* s = src + (size_t)k*Ndim + n;
    float4 v0 = *(const float4*)s;
    float4 v1 = *(const float4*)(s+4);
    int gp = (g & 8) | ((g & 7) ^ (kr & 7));
    __nv_bfloat162* d = (__nv_bfloat162*)(dst + ((((size_t)rest)*64 + kr)*128) + gp*8);
    d[0] = __floats2bfloat162_rn(v0.x, v0.y);
    d[1] = __floats2bfloat162_rn(v0.z, v0.w);
    d[2] = __floats2bfloat162_rn(v1.x, v1.y);
    d[3] = __floats2bfloat162_rn(v1.z, v1.w);
}

// ---------- bf16 mma GEMM, 128x128 tile, KC=64, bulk-copy 4-stage mbarrier ring ----------
#define GST 4
#define KCHK 64
#define ATILE_B (128*128)              // 16 KB
#define BTILE_B (64*256)               // 16 KB
#define STAGE_B (ATILE_B + BTILE_B)    // 32 KB
#define GEMM_SMEM (GST*STAGE_B + 64)

template<int MODE>
__global__ __launch_bounds__(256,1) void gemm_bulk_kernel(const float* __restrict__ bias,
                                                          float* __restrict__ Cf){
    constexpr int N  = (MODE==0) ? MLPD : DIMN;
    constexpr int K  = (MODE==0) ? DIMN : MLPD;
    constexpr int nk = K / KCHK;
    const __nv_bfloat16* Ach = (MODE==0) ? g_xn2 : g_hbuf;   // [kc][ROWS][64]
    const __nv_bfloat16* Bpk = (MODE==0) ? g_w1p : g_w2p;    // [nb][kc][64][128]

    extern __shared__ __align__(128) char smem[];
    uint32_t sbase = smem_u32(smem);
    uint32_t mbar  = sbase + GST*STAGE_B;
    int tid = threadIdx.x, warp = tid >> 5, lane = tid & 31;
    int bm = blockIdx.y * 128;
    int nb = blockIdx.x;
    int wm = (warp >> 2) * 64;
    int wn = (warp & 3) * 32;

    if (tid == 0){
        #pragma unroll
        for (int s=0; s<GST; s++) mbar_init(mbar + 8*s, 1);
        FENCE_ASYNC();
    }
    __syncthreads();

    auto fill = [&](int st, int kc){
        uint32_t dstA = sbase + st*STAGE_B;
        uint32_t mb = mbar + 8*st;
        mbar_expect_tx(mb, STAGE_B);
        bulk_g2s(dstA, (const char*)Ach + ((size_t)kc*ROWS + bm)*128, ATILE_B, mb);
        bulk_g2s(dstA + ATILE_B, (const char*)Bpk + ((size_t)nb*nk + kc)*(size_t)BTILE_B, BTILE_B, mb);
    };

    if (tid == 0){
        #pragma unroll
        for (int p=0; p<GST-1; p++) fill(p, p);
    }

    float acc[4][4][4];
    #pragma unroll
    for (int i=0;i<4;i++)
        #pragma unroll
        for (int j=0;j<4;j++)
            #pragma unroll
            for (int k=0;k<4;k++) acc[i][j][k]=0.f;

    for (int kt = 0; kt < nk; kt++){
        int cur = kt & (GST-1);
        __syncthreads();                       // everyone done reading stage (kt-1)&3
        if (tid == 0 && kt + GST - 1 < nk) fill((kt + GST - 1) & (GST-1), kt + GST - 1);
        mbar_wait(mbar + 8*cur, (kt >> 2) & 1);

        uint32_t As = sbase + cur*STAGE_B;
        uint32_t Bs = As + ATILE_B;

        #pragma unroll
        for (int ks=0; ks<4; ks++){
            uint32_t af[4][4], bfr[4][2];
            #pragma unroll
            for (int mi=0; mi<4; mi++){
                int r = wm + mi*16 + (lane & 15);
                int g = ks*2 + (lane >> 4);
                int gp = g ^ (r & 7);
                ldsm_x4(af[mi][0],af[mi][1],af[mi][2],af[mi][3],
                        As + r*128 + gp*16);
            }
            #pragma unroll
            for (int nj=0; nj<2; nj++){
                int r = ks*16 + (((lane>>3)&1) << 3) + (lane & 7);
                int c = wn + nj*16 + ((lane >> 4) << 3);
                int g = c >> 3;
                int gp = (g & 8) | ((g & 7) ^ (r & 7));
                uint32_t t0,t1,t2,t3;
                ldsm_x4_t(t0,t1,t2,t3, Bs + r*256 + gp*16);
                bfr[nj*2][0]=t0; bfr[nj*2][1]=t1;
                bfr[nj*2+1][0]=t2; bfr[nj*2+1][1]=t3;
            }
            #pragma unroll
            for (int mi=0; mi<4; mi++)
                #pragma unroll
                for (int ni=0; ni<4; ni++)
                    mma_bf16(acc[mi][ni], af[mi][0],af[mi][1],af[mi][2],af[mi][3],
                             bfr[ni][0], bfr[ni][1]);
        }
    }

    // epilogue
    #pragma unroll
    for (int mi=0; mi<4; mi++){
        #pragma unroll
        for (int ni=0; ni<4; ni++){
            int r = bm + wm + mi*16 + (lane >> 2);
            int c = nb*128 + wn + ni*8 + (lane & 3)*2;
            float* a = acc[mi][ni];
            float bx = bias[c], by = bias[c+1];
            if (MODE == 0){
                // write gelu(acc+bias) into chunked swizzled hbuf layout
                float v0 = gelu_exact(a[0]+bx), v1 = gelu_exact(a[1]+by);
                float v2 = gelu_exact(a[2]+bx), v3 = gelu_exact(a[3]+by);
                int kc = c >> 6, cc = c & 63, g = cc >> 3;
                int gp = g ^ (r & 7);     // (r+8)&7 == r&7
                size_t base0 = ((size_t)kc*ROWS + r)*128 + gp*16 + (cc & 7)*2;
                __nv_bfloat162 p0 = __floats2bfloat162_rn(v0, v1);
                __nv_bfloat162 p1 = __floats2bfloat162_rn(v2, v3);
                *(__nv_bfloat162*)((char*)g_hbuf + base0)         = p0;
                *(__nv_bfloat162*)((char*)g_hbuf + base0 + 8*128) = p1;
            } else {
                size_t o0 = (size_t)r*N + c, o1 = (size_t)(r+8)*N + c;
                float2 r0 = *(const float2*)(g_x2 + o0);
                float2 r1 = *(const float2*)(g_x2 + o1);
                *(float2*)(Cf + o0) = make_float2(a[0]+bx+r0.x, a[1]+by+r0.y);
                *(float2*)(Cf + o1) = make_float2(a[2]+bx+r1.x, a[3]+by+r1.y);
            }
        }
    }
}

// ---------------- launch ----------------
extern "C" void kernel_launch(void* const* d_in, const int* in_sizes, int n_in,
                              void* d_out, int out_size){
    const float* x     = (const float*)d_in[0];
    const float* Wq    = (const float*)d_in[1];
    const float* Wk    = (const float*)d_in[2];
    const float* Wv    = (const float*)d_in[3];
    const float* E     = (const float*)d_in[4];
    const float* Fm    = (const float*)d_in[5];
    const float* Wo    = (const float*)d_in[6];
    const float* bo    = (const float*)d_in[7];
    const float* ln1_g = (const float*)d_in[8];
    const float* ln1_b = (const float*)d_in[9];
    const float* ln2_g = (const float*)d_in[10];
    const float* ln2_b = (const float*)d_in[11];
    const float* W1    = (const float*)d_in[12];
    const float* b1    = (const float*)d_in[13];
    const float* W2    = (const float*)d_in[14];
    const float* b2    = (const float*)d_in[15];
    float* out = (float*)d_out;

    cudaFuncSetAttribute(gemm_bulk_kernel<0>, cudaFuncAttributeMaxDynamicSharedMemorySize, GEMM_SMEM);
    cudaFuncSetAttribute(gemm_bulk_kernel<1>, cudaFuncAttributeMaxDynamicSharedMemorySize, GEMM_SMEM);

    zero_small_kernel<<<16, 256>>>();
    ln1_kernel<<<ROWS, 256>>>(x, ln1_g, ln1_b);
    colsum_xn_kernel<<<dim3(BATCH, 32), 1024>>>();
    colsum_ef_kernel<<<dim3(2, 16), 64>>>(E, Fm);
    gemv_AAp_kernel<<<dim3(4, BATCH), 256>>>(Wk, Wv);
    compute_u_kernel<<<dim3(BATCH, 64), 256>>>(Wq);
    compute_G_kernel<<<dim3(BATCH, HEADS), 256>>>(Wo);
    attn_apply_kernel<<<ROWS, 256>>>(x, bo, ln2_g, ln2_b);

    pack_w_kernel<<<(DIMN*MLPD/8 + 255)/256, 256>>>(W1, g_w1p, DIMN, MLPD);
    pack_w_kernel<<<(MLPD*DIMN/8 + 255)/256, 256>>>(W2, g_w2p, MLPD, DIMN);

    gemm_bulk_kernel<0><<<dim3(MLPD/128, ROWS/128), 256, GEMM_SMEM>>>(b1, nullptr);
    gemm_bulk_kernel<1><<<dim3(DIMN/128, ROWS/128), 256, GEMM_SMEM>>>(b2, out);
}